// round 11
// baseline (speedup 1.0000x reference)
#include <cuda_runtime.h>
#include <cuda_fp16.h>
#include <stdint.h>

#define KG_MAX 200000
#define B_MAX  20000
#define E_MAX  640000
#define IN_DIM 256
#define OUT_DIM 128

// ---------------- device scratch ----------------
__device__ int   g_is64;
__device__ __align__(16) float g_vL[IN_DIM];
__device__ __align__(16) float g_vR[IN_DIM];
__device__ float g_cLR;
__device__ float g_dR[KG_MAX];
__device__ float g_sL[B_MAX];
__device__ int   g_cnt[B_MAX];
__device__ int   g_cur[B_MAX];
__device__ int   g_off[B_MAX + 1];
__device__ int   g_csr[E_MAX];
__device__ __align__(16) __half g_enth[(size_t)KG_MAX * IN_DIM];
__device__ __align__(16) __half g_Yh[(size_t)B_MAX * IN_DIM];
__device__ __align__(16) unsigned g_Wfrag[16 * 16 * 32 * 2];

__device__ __forceinline__ int ld_row(const void* p, int e, int is64) {
    return is64 ? (int)((const long long*)p)[e] : ((const int*)p)[e];
}
__device__ __forceinline__ int ld_col(const void* p, int E, int e, int is64) {
    return is64 ? (int)((const long long*)p)[(long long)E + e]
                : ((const int*)p)[E + e];
}

// ---------------- k_prep ----------------
__global__ void k_prep(const void* __restrict__ bids,
                       const float* __restrict__ W,
                       const float* __restrict__ bias,
                       const float* __restrict__ wa,
                       int B) {
    int t = threadIdx.x;  // 256
    __shared__ int s_nz;
    if (t == 0) s_nz = 0;
    __syncthreads();
    const unsigned int* u = (const unsigned int*)bids;
    if (u[2 * t + 1] != 0u) atomicOr(&s_nz, 1);
    __syncthreads();
    if (t == 0) g_is64 = s_nz ? 0 : 1;

    float vl = 0.f, vr = 0.f;
#pragma unroll 4
    for (int n = 0; n < OUT_DIM; n++) {
        float w = W[n * IN_DIM + t];
        vl = fmaf(w, wa[n], vl);
        vr = fmaf(w, wa[OUT_DIM + n], vr);
    }
    g_vL[t] = vl;
    g_vR[t] = vr;

    __shared__ float sr[256];
    sr[t] = (t < OUT_DIM) ? bias[t] * (wa[t] + wa[t + OUT_DIM]) : 0.f;
    __syncthreads();
    for (int off = 128; off > 0; off >>= 1) {
        if (t < off) sr[t] += sr[t + off];
        __syncthreads();
    }
    if (t == 0) g_cLR = sr[0];

    // pack W into mma.m16n8k16 B-fragment order (fp16)
    for (int f = t; f < 16 * 16 * 32 * 2; f += 256) {
        int q = f & 1;
        int lane = (f >> 1) & 31;
        int nf = (f >> 6) & 15;
        int ks = f >> 10;
        int n = nf * 8 + (lane >> 2);
        int k = ks * 16 + (lane & 3) * 2 + (q ? 8 : 0);
        __half2 h = __floats2half2_rn(W[n * IN_DIM + k], W[n * IN_DIM + k + 1]);
        g_Wfrag[f] = *(unsigned*)&h;
    }
    for (int i = t; i < B; i += 256) { g_cnt[i] = 0; g_cur[i] = 0; }
}

// ---------------- k_fused v2: 4 rows/warp dR + fp16 convert; sL -----------
// dR blocks: 32 rows/block. Lane l: sub = l>>3 -> row, li = l&7 -> cols
// [li*32, li*32+32). 8 independent LDG.128 per lane (MLP 8); dR reduce is
// 3 shfl-xor within the 8-lane group; fp16 stores coalesced (512B/row).
__global__ void __launch_bounds__(256) k_fused(
        const float* __restrict__ ent, const void* __restrict__ bids,
        int KG, int B, int nbdr) {
    int bid = blockIdx.x;
    int t = threadIdx.x, w = t >> 5, lane = t & 31;
    if (bid < nbdr) {
        int sub = lane >> 3, li = lane & 7;
        int row = bid * 32 + w * 4 + sub;
        if (row < KG) {
            const float4* xp = (const float4*)(ent + (size_t)row * IN_DIM + li * 32);
            const float4* vp = (const float4*)&g_vR[li * 32];
            float4 x[8];
#pragma unroll
            for (int j = 0; j < 8; j++) x[j] = xp[j];
            float d = 0.f;
#pragma unroll
            for (int j = 0; j < 8; j++) {
                float4 v = vp[j];
                d = fmaf(x[j].x, v.x, d);
                d = fmaf(x[j].y, v.y, d);
                d = fmaf(x[j].z, v.z, d);
                d = fmaf(x[j].w, v.w, d);
            }
            // reduce over li (lanes differing in low 3 bits share a row)
            d += __shfl_xor_sync(0xffffffffu, d, 1);
            d += __shfl_xor_sync(0xffffffffu, d, 2);
            d += __shfl_xor_sync(0xffffffffu, d, 4);
            if (li == 0) g_dR[row] = d;
            // fp16 convert + store: 4 uint4 = 64B per lane, coalesced per row
            uint4* op = ((uint4*)g_enth) + (size_t)row * 32 + li * 4;
#pragma unroll
            for (int j = 0; j < 4; j++) {
                __half2 h0 = __floats2half2_rn(x[2 * j].x, x[2 * j].y);
                __half2 h1 = __floats2half2_rn(x[2 * j].z, x[2 * j].w);
                __half2 h2 = __floats2half2_rn(x[2 * j + 1].x, x[2 * j + 1].y);
                __half2 h3 = __floats2half2_rn(x[2 * j + 1].z, x[2 * j + 1].w);
                uint4 q;
                q.x = *(unsigned*)&h0; q.y = *(unsigned*)&h1;
                q.z = *(unsigned*)&h2; q.w = *(unsigned*)&h3;
                op[j] = q;
            }
        }
    } else {
        int r = (bid - nbdr) * 8 + w;
        if (r < B) {
            long long gi = g_is64 ? ((const long long*)bids)[r]
                                  : (long long)((const int*)bids)[r];
            const float* x = ent + gi * (long long)IN_DIM + lane * 8;
            float4 x0 = *(const float4*)x;
            float4 x1 = *(const float4*)(x + 4);
            float4 l0 = *(const float4*)&g_vL[lane * 8];
            float4 l1 = *(const float4*)&g_vL[lane * 8 + 4];
            float d = x0.x * l0.x + x0.y * l0.y + x0.z * l0.z + x0.w * l0.w
                    + x1.x * l1.x + x1.y * l1.y + x1.z * l1.z + x1.w * l1.w;
#pragma unroll
            for (int o = 16; o > 0; o >>= 1)
                d += __shfl_xor_sync(0xffffffffu, d, o);
            if (lane == 0) g_sL[r] = d + g_cLR;
        }
    }
}

// ---------------- CSR chain (stream B) ----------------
__global__ void k_hist(const void* __restrict__ ei, int E) {
    int e = blockIdx.x * blockDim.x + threadIdx.x;
    if (e >= E) return;
    int r = ld_row(ei, e, g_is64);
    atomicAdd(&g_cnt[r], 1);
}

__global__ void k_scan(int B) {
    __shared__ int s[1024];
    int t = threadIdx.x;
    int CH = (B + 1023) >> 10;
    int lo = t * CH, hi = min(lo + CH, B);
    int sum = 0;
    for (int i = lo; i < hi; i++) sum += g_cnt[i];
    s[t] = sum;
    __syncthreads();
    for (int off = 1; off < 1024; off <<= 1) {
        int v = (t >= off) ? s[t - off] : 0;
        __syncthreads();
        s[t] += v;
        __syncthreads();
    }
    int run = (t == 0) ? 0 : s[t - 1];
    for (int i = lo; i < hi; i++) { g_off[i] = run; run += g_cnt[i]; }
    if (t == 1023) g_off[B] = s[1023];
}

__global__ void k_scatter(const void* __restrict__ ei, int E) {
    int e = blockIdx.x * blockDim.x + threadIdx.x;
    if (e >= E) return;
    int r = ld_row(ei, e, g_is64);
    int pos = atomicAdd(&g_cur[r], 1);
    g_csr[g_off[r] + pos] = e;
}

// ---------------- warp-register bitonic sort of 64 ints (2/lane) -----------
__device__ __forceinline__ void bitonic64(int& v0, int& v1, int lane) {
#pragma unroll
    for (int k = 2; k <= 32; k <<= 1) {
#pragma unroll
        for (int j = k >> 1; j > 0; j >>= 1) {
            bool low = ((lane & j) == 0);
            int x0 = __shfl_xor_sync(0xffffffffu, v0, j);
            bool asc0 = ((lane & k) == 0);
            v0 = (asc0 == low) ? min(v0, x0) : max(v0, x0);
            int x1 = __shfl_xor_sync(0xffffffffu, v1, j);
            bool asc1 = (k == 32) ? false : asc0;
            v1 = (asc1 == low) ? min(v1, x1) : max(v1, x1);
        }
    }
    { int mn = min(v0, v1), mx = max(v0, v1); v0 = mn; v1 = mx; }
#pragma unroll
    for (int j = 16; j > 0; j >>= 1) {
        bool low = ((lane & j) == 0);
        int x0 = __shfl_xor_sync(0xffffffffu, v0, j);
        v0 = low ? min(v0, x0) : max(v0, x0);
        int x1 = __shfl_xor_sync(0xffffffffu, v1, j);
        v1 = low ? min(v1, x1) : max(v1, x1);
    }
}

// ---------------- k_agg (R9 structure, 1 warp/row) ----------------
__global__ void __launch_bounds__(256) k_agg(const void* __restrict__ ei,
                                             int E, int B) {
    __shared__ int   s_e[8][128];
    __shared__ float s_a[8][128];
    int t = threadIdx.x, w = t >> 5, lane = t & 31;
    int r = blockIdx.x * 8 + w;
    if (r >= B) return;
    int is64 = g_is64;
    int off0 = g_off[r];
    int deg = g_off[r + 1] - off0;
    float base = g_sL[r];

    const uint4* eh = (const uint4*)g_enth;
    float4 A0 = make_float4(0.f, 0.f, 0.f, 0.f);
    float4 A1 = make_float4(0.f, 0.f, 0.f, 0.f);
    float asum = 0.f;

#define ACC(q, a) do { \
        float2 f0 = __half22float2(*(__half2*)&(q).x); \
        float2 f1 = __half22float2(*(__half2*)&(q).y); \
        float2 f2 = __half22float2(*(__half2*)&(q).z); \
        float2 f3 = __half22float2(*(__half2*)&(q).w); \
        A0.x = fmaf((a), f0.x, A0.x); A0.y = fmaf((a), f0.y, A0.y); \
        A0.z = fmaf((a), f1.x, A0.z); A0.w = fmaf((a), f1.y, A0.w); \
        A1.x = fmaf((a), f2.x, A1.x); A1.y = fmaf((a), f2.y, A1.y); \
        A1.z = fmaf((a), f3.x, A1.z); A1.w = fmaf((a), f3.y, A1.w); \
    } while (0)

#define GATHER_LOOP() do { \
        int i = 0; \
        for (; i + 4 <= deg; i += 4) { \
            int c0 = s_e[w][i],     c1 = s_e[w][i + 1]; \
            int c2 = s_e[w][i + 2], c3 = s_e[w][i + 3]; \
            uint4 q0 = __ldg(&eh[(size_t)c0 * 32 + lane]); \
            uint4 q1 = __ldg(&eh[(size_t)c1 * 32 + lane]); \
            uint4 q2 = __ldg(&eh[(size_t)c2 * 32 + lane]); \
            uint4 q3 = __ldg(&eh[(size_t)c3 * 32 + lane]); \
            float a0 = s_a[w][i],     a1 = s_a[w][i + 1]; \
            float a2 = s_a[w][i + 2], a3 = s_a[w][i + 3]; \
            ACC(q0, a0); ACC(q1, a1); ACC(q2, a2); ACC(q3, a3); \
        } \
        for (; i < deg; i++) { \
            int c = s_e[w][i]; \
            float a = s_a[w][i]; \
            uint4 q = __ldg(&eh[(size_t)c * 32 + lane]); \
            ACC(q, a); \
        } \
    } while (0)

    if (deg <= 64) {
        int v0 = (lane < deg) ? g_csr[off0 + lane] : 0x7fffffff;
        int v1 = (32 + lane < deg) ? g_csr[off0 + 32 + lane] : 0x7fffffff;
        bitonic64(v0, v1, lane);
        float ap = 0.f;
        if (lane < deg) {
            int c = ld_col(ei, E, v0, is64);
            float s = base + g_dR[c];
            float v = s >= 0.f ? s : 0.2f * s;
            float a = __expf(-v);
            s_e[w][lane] = c; s_a[w][lane] = a;
            ap += a;
        }
        if (32 + lane < deg) {
            int c = ld_col(ei, E, v1, is64);
            float s = base + g_dR[c];
            float v = s >= 0.f ? s : 0.2f * s;
            float a = __expf(-v);
            s_e[w][32 + lane] = c; s_a[w][32 + lane] = a;
            ap += a;
        }
#pragma unroll
        for (int o = 16; o > 0; o >>= 1)
            ap += __shfl_xor_sync(0xffffffffu, ap, o);
        asum = ap;
        __syncwarp();
        GATHER_LOOP();
    } else if (deg <= 128) {
        int P = 1;
        while (P < deg) P <<= 1;
        for (int i = lane; i < P; i += 32)
            s_e[w][i] = (i < deg) ? g_csr[off0 + i] : 0x7fffffff;
        __syncwarp();
        for (int k = 2; k <= P; k <<= 1) {
            for (int j = k >> 1; j > 0; j >>= 1) {
                for (int i = lane; i < P; i += 32) {
                    int ixj = i ^ j;
                    if (ixj > i) {
                        int a = s_e[w][i], c = s_e[w][ixj];
                        bool up = ((i & k) == 0);
                        if ((a > c) == up) { s_e[w][i] = c; s_e[w][ixj] = a; }
                    }
                }
                __syncwarp();
            }
        }
        float ap = 0.f;
        for (int i = lane; i < deg; i += 32) {
            int e = s_e[w][i];
            int c = ld_col(ei, E, e, is64);
            float s = base + g_dR[c];
            float v = s >= 0.f ? s : 0.2f * s;
            float a = __expf(-v);
            s_e[w][i] = c;
            s_a[w][i] = a;
            ap += a;
        }
#pragma unroll
        for (int o = 16; o > 0; o >>= 1)
            ap += __shfl_xor_sync(0xffffffffu, ap, o);
        asum = ap;
        __syncwarp();
        GATHER_LOOP();
    } else {
        // deterministic fallback: increasing edge-id selection (rare)
        int last = -1;
        for (int rk = 0; rk < deg; rk++) {
            int m = 0x7fffffff;
            for (int i = lane; i < deg; i += 32) {
                int ec = g_csr[off0 + i];
                if (ec > last && ec < m) m = ec;
            }
#pragma unroll
            for (int o = 16; o > 0; o >>= 1)
                m = min(m, __shfl_xor_sync(0xffffffffu, m, o));
            int c = ld_col(ei, E, m, is64);
            float s = base + g_dR[c];
            float v = s >= 0.f ? s : 0.2f * s;
            float a = __expf(-v);
            uint4 q = __ldg(&eh[(size_t)c * 32 + lane]);
            asum += a;
            ACC(q, a);
            last = m;
        }
    }
#undef GATHER_LOOP
#undef ACC

    float inv = 1.0f / asum;
    __half2 h0 = __floats2half2_rn(A0.x * inv, A0.y * inv);
    __half2 h1 = __floats2half2_rn(A0.z * inv, A0.w * inv);
    __half2 h2 = __floats2half2_rn(A1.x * inv, A1.y * inv);
    __half2 h3 = __floats2half2_rn(A1.z * inv, A1.w * inv);
    uint4 q;
    q.x = *(unsigned*)&h0; q.y = *(unsigned*)&h1;
    q.z = *(unsigned*)&h2; q.w = *(unsigned*)&h3;
    ((uint4*)g_Yh)[(size_t)r * 32 + lane] = q;
}

// ---------------- k_gemm: HMMA m16n8k16 ----------------
__global__ void __launch_bounds__(256) k_gemm(const float* __restrict__ bias,
                                              const float* __restrict__ prelu,
                                              float* __restrict__ out, int M) {
    int tid = threadIdx.x;
    int wid = tid >> 5, lane = tid & 31;
    int gid = lane >> 2, tig = lane & 3;
    int mbase = blockIdx.x * 128 + wid * 16;
    int r0 = mbase + gid, r1 = r0 + 8;
    bool p0 = r0 < M, p1 = r1 < M;

    float acc[16][4];
#pragma unroll
    for (int nf = 0; nf < 16; nf++)
#pragma unroll
        for (int j = 0; j < 4; j++) acc[nf][j] = 0.f;

    const __half* Yh = g_Yh;
    const uint2* Wf = (const uint2*)g_Wfrag;

    for (int ks = 0; ks < 16; ks++) {
        int k0 = ks * 16 + tig * 2;
        unsigned a0 = p0 ? *(const unsigned*)&Yh[(size_t)r0 * IN_DIM + k0] : 0u;
        unsigned a1 = p1 ? *(const unsigned*)&Yh[(size_t)r1 * IN_DIM + k0] : 0u;
        unsigned a2 = p0 ? *(const unsigned*)&Yh[(size_t)r0 * IN_DIM + k0 + 8] : 0u;
        unsigned a3 = p1 ? *(const unsigned*)&Yh[(size_t)r1 * IN_DIM + k0 + 8] : 0u;
#pragma unroll
        for (int nf = 0; nf < 16; nf++) {
            uint2 bb = __ldg(&Wf[(ks * 16 + nf) * 32 + lane]);
            asm volatile(
                "mma.sync.aligned.m16n8k16.row.col.f32.f16.f16.f32 "
                "{%0,%1,%2,%3}, {%4,%5,%6,%7}, {%8,%9}, {%0,%1,%2,%3};"
                : "+f"(acc[nf][0]), "+f"(acc[nf][1]),
                  "+f"(acc[nf][2]), "+f"(acc[nf][3])
                : "r"(a0), "r"(a1), "r"(a2), "r"(a3),
                  "r"(bb.x), "r"(bb.y));
        }
    }

    float pw = prelu[0];
#pragma unroll
    for (int nf = 0; nf < 16; nf++) {
        int n0 = nf * 8 + tig * 2;
        float bv0 = __ldg(&bias[n0]), bv1 = __ldg(&bias[n0 + 1]);
        if (p0) {
            float v0 = acc[nf][0] + bv0, v1 = acc[nf][1] + bv1;
            float2 o;
            o.x = v0 >= 0.f ? v0 : pw * v0;
            o.y = v1 >= 0.f ? v1 : pw * v1;
            *(float2*)&out[(size_t)r0 * OUT_DIM + n0] = o;
        }
        if (p1) {
            float v2 = acc[nf][2] + bv0, v3 = acc[nf][3] + bv1;
            float2 o;
            o.x = v2 >= 0.f ? v2 : pw * v2;
            o.y = v3 >= 0.f ? v3 : pw * v3;
            *(float2*)&out[(size_t)r1 * OUT_DIM + n0] = o;
        }
    }
}

// ---------------- launch (R9 structure: CSR chain forked on stream B) ------
extern "C" void kernel_launch(void* const* d_in, const int* in_sizes, int n_in,
                              void* d_out, int out_size) {
    const float* ent  = (const float*)d_in[0];
    const void*  bids = d_in[1];
    const void*  ei   = d_in[2];
    const float* W    = (const float*)d_in[3];
    const float* bias = (const float*)d_in[4];
    const float* wa   = (const float*)d_in[5];
    const float* pw   = (const float*)d_in[6];

    int KG = in_sizes[0] / IN_DIM;
    int B  = in_sizes[1];
    int E  = in_sizes[2] / 2;
    if (KG > KG_MAX) KG = KG_MAX;
    if (B > B_MAX) B = B_MAX;
    if (E > E_MAX) E = E_MAX;

    int nbdr = (KG + 31) / 32;
    int nbsl = (B + 7) / 8;

    cudaStream_t s2;
    cudaEvent_t ev1, ev2;
    cudaStreamCreateWithFlags(&s2, cudaStreamNonBlocking);
    cudaEventCreateWithFlags(&ev1, cudaEventDisableTiming);
    cudaEventCreateWithFlags(&ev2, cudaEventDisableTiming);

    k_prep<<<1, 256>>>(bids, W, bias, wa, B);
    cudaEventRecord(ev1, 0);
    cudaStreamWaitEvent(s2, ev1, 0);

    // stream B: CSR chain (atomic/latency-bound)
    k_hist<<<(E + 255) / 256, 256, 0, s2>>>(ei, E);
    k_scan<<<1, 1024, 0, s2>>>(B);
    k_scatter<<<(E + 255) / 256, 256, 0, s2>>>(ei, E);
    cudaEventRecord(ev2, s2);

    // stream A (default): BW-bound embedding pass, concurrent with CSR chain
    k_fused<<<nbdr + nbsl, 256>>>(ent, bids, KG, B, nbdr);

    cudaStreamWaitEvent(0, ev2, 0);
    k_agg<<<(B + 7) / 8, 256>>>(ei, E, B);
    k_gemm<<<(B + 127) / 128, 256>>>(bias, pw, (float*)d_out, B);

    cudaEventDestroy(ev1);
    cudaEventDestroy(ev2);
    cudaStreamDestroy(s2);
}

// round 12
// speedup vs baseline: 1.0880x; 1.0880x over previous
#include <cuda_runtime.h>
#include <cuda_fp16.h>
#include <stdint.h>

#define KG_MAX 200000
#define B_MAX  20000
#define E_MAX  640000
#define IN_DIM 256
#define OUT_DIM 128

// ---------------- device scratch ----------------
__device__ int   g_is64;
__device__ __align__(16) float g_vL[IN_DIM];
__device__ __align__(16) float g_vR[IN_DIM];
__device__ float g_cLR;
__device__ float g_dR[KG_MAX];
__device__ float g_sL[B_MAX];
__device__ int   g_cnt[B_MAX];
__device__ int   g_cur[B_MAX];
__device__ int   g_off[B_MAX + 1];
__device__ int   g_csr[E_MAX];
__device__ __align__(16) __half g_enth[(size_t)KG_MAX * IN_DIM];
__device__ __align__(16) __half g_Yh[(size_t)B_MAX * IN_DIM];
__device__ __align__(16) unsigned g_Wfrag[16 * 16 * 32 * 2];

__device__ __forceinline__ int ld_row(const void* p, int e, int is64) {
    return is64 ? (int)((const long long*)p)[e] : ((const int*)p)[e];
}
__device__ __forceinline__ int ld_col(const void* p, int E, int e, int is64) {
    return is64 ? (int)((const long long*)p)[(long long)E + e]
                : ((const int*)p)[E + e];
}

__device__ __forceinline__ uint2 f4_to_h4(float4 x) {
    __half2 h0 = __floats2half2_rn(x.x, x.y);
    __half2 h1 = __floats2half2_rn(x.z, x.w);
    uint2 q;
    q.x = *(unsigned*)&h0;
    q.y = *(unsigned*)&h1;
    return q;
}

// ---------------- k_prep ----------------
__global__ void k_prep(const void* __restrict__ bids,
                       const float* __restrict__ W,
                       const float* __restrict__ bias,
                       const float* __restrict__ wa,
                       int B) {
    int t = threadIdx.x;  // 256
    __shared__ int s_nz;
    if (t == 0) s_nz = 0;
    __syncthreads();
    const unsigned int* u = (const unsigned int*)bids;
    if (u[2 * t + 1] != 0u) atomicOr(&s_nz, 1);
    __syncthreads();
    if (t == 0) g_is64 = s_nz ? 0 : 1;

    float vl = 0.f, vr = 0.f;
#pragma unroll 4
    for (int n = 0; n < OUT_DIM; n++) {
        float w = W[n * IN_DIM + t];
        vl = fmaf(w, wa[n], vl);
        vr = fmaf(w, wa[OUT_DIM + n], vr);
    }
    g_vL[t] = vl;
    g_vR[t] = vr;

    __shared__ float sr[256];
    sr[t] = (t < OUT_DIM) ? bias[t] * (wa[t] + wa[t + OUT_DIM]) : 0.f;
    __syncthreads();
    for (int off = 128; off > 0; off >>= 1) {
        if (t < off) sr[t] += sr[t + off];
        __syncthreads();
    }
    if (t == 0) g_cLR = sr[0];

    // pack W into mma.m16n8k16 B-fragment order (fp16)
    for (int f = t; f < 16 * 16 * 32 * 2; f += 256) {
        int q = f & 1;
        int lane = (f >> 1) & 31;
        int nf = (f >> 6) & 15;
        int ks = f >> 10;
        int n = nf * 8 + (lane >> 2);
        int k = ks * 16 + (lane & 3) * 2 + (q ? 8 : 0);
        __half2 h = __floats2half2_rn(W[n * IN_DIM + k], W[n * IN_DIM + k + 1]);
        g_Wfrag[f] = *(unsigned*)&h;
    }
    for (int i = t; i < B; i += 256) { g_cnt[i] = 0; g_cur[i] = 0; }
}

// ---------------- k_fused v3: 4 rows/warp, coalesced, MLP=8 ----------------
// Load (rr,p): float4 at ent_f4[(row0+rr)*64 + p*32 + lane] -> 32 lanes x 16B
// contiguous (4 full 128B lines per instruction). 8 independent loads, then
// 4 interleaved butterfly reductions for dR, then 8 coalesced STG.64 fp16.
__global__ void __launch_bounds__(256) k_fused(
        const float* __restrict__ ent, const void* __restrict__ bids,
        int KG, int B, int nbdr) {
    int bid = blockIdx.x;
    int t = threadIdx.x, w = t >> 5, lane = t & 31;
    if (bid < nbdr) {
        int row0 = bid * 32 + w * 4;
        if (row0 + 3 < KG) {
            const float4* ef4 = (const float4*)ent;
            size_t rb = (size_t)row0 * 64 + lane;
            float4 a0 = ef4[rb];        float4 b0 = ef4[rb + 32];
            float4 a1 = ef4[rb + 64];   float4 b1 = ef4[rb + 96];
            float4 a2 = ef4[rb + 128];  float4 b2 = ef4[rb + 160];
            float4 a3 = ef4[rb + 192];  float4 b3 = ef4[rb + 224];

            const float4* vf4 = (const float4*)g_vR;
            float4 v0 = vf4[lane], v1 = vf4[32 + lane];

            float d0 = a0.x * v0.x + a0.y * v0.y + a0.z * v0.z + a0.w * v0.w
                     + b0.x * v1.x + b0.y * v1.y + b0.z * v1.z + b0.w * v1.w;
            float d1 = a1.x * v0.x + a1.y * v0.y + a1.z * v0.z + a1.w * v0.w
                     + b1.x * v1.x + b1.y * v1.y + b1.z * v1.z + b1.w * v1.w;
            float d2 = a2.x * v0.x + a2.y * v0.y + a2.z * v0.z + a2.w * v0.w
                     + b2.x * v1.x + b2.y * v1.y + b2.z * v1.z + b2.w * v1.w;
            float d3 = a3.x * v0.x + a3.y * v0.y + a3.z * v0.z + a3.w * v0.w
                     + b3.x * v1.x + b3.y * v1.y + b3.z * v1.z + b3.w * v1.w;
#pragma unroll
            for (int o = 16; o > 0; o >>= 1) {
                d0 += __shfl_xor_sync(0xffffffffu, d0, o);
                d1 += __shfl_xor_sync(0xffffffffu, d1, o);
                d2 += __shfl_xor_sync(0xffffffffu, d2, o);
                d3 += __shfl_xor_sync(0xffffffffu, d3, o);
            }
            if (lane == 0) {
                g_dR[row0]     = d0;
                g_dR[row0 + 1] = d1;
                g_dR[row0 + 2] = d2;
                g_dR[row0 + 3] = d3;
            }
            uint2* oh = (uint2*)g_enth;   // 64 uint2 per row
            size_t ob = (size_t)row0 * 64 + lane;
            oh[ob]       = f4_to_h4(a0);  oh[ob + 32]  = f4_to_h4(b0);
            oh[ob + 64]  = f4_to_h4(a1);  oh[ob + 96]  = f4_to_h4(b1);
            oh[ob + 128] = f4_to_h4(a2);  oh[ob + 160] = f4_to_h4(b2);
            oh[ob + 192] = f4_to_h4(a3);  oh[ob + 224] = f4_to_h4(b3);
        } else {
            // tail: per-row fallback (v1 style, one row per sub-group pass)
            for (int rr = 0; rr < 4; rr++) {
                int row = row0 + rr;
                if (row >= KG) break;
                const float* x = ent + (size_t)row * IN_DIM + lane * 8;
                float4 x0 = *(const float4*)x;
                float4 x1 = *(const float4*)(x + 4);
                float4 r0 = *(const float4*)&g_vR[lane * 8];
                float4 r1 = *(const float4*)&g_vR[lane * 8 + 4];
                float d = x0.x * r0.x + x0.y * r0.y + x0.z * r0.z + x0.w * r0.w
                        + x1.x * r1.x + x1.y * r1.y + x1.z * r1.z + x1.w * r1.w;
#pragma unroll
                for (int o = 16; o > 0; o >>= 1)
                    d += __shfl_xor_sync(0xffffffffu, d, o);
                if (lane == 0) g_dR[row] = d;
                uint4 q;
                uint2 qa = f4_to_h4(x0), qb = f4_to_h4(x1);
                q.x = qa.x; q.y = qa.y; q.z = qb.x; q.w = qb.y;
                ((uint4*)g_enth)[(size_t)row * 32 + lane] = q;
            }
        }
    } else {
        int r = (bid - nbdr) * 8 + w;
        if (r < B) {
            long long gi = g_is64 ? ((const long long*)bids)[r]
                                  : (long long)((const int*)bids)[r];
            const float* x = ent + gi * (long long)IN_DIM + lane * 8;
            float4 x0 = *(const float4*)x;
            float4 x1 = *(const float4*)(x + 4);
            float4 l0 = *(const float4*)&g_vL[lane * 8];
            float4 l1 = *(const float4*)&g_vL[lane * 8 + 4];
            float d = x0.x * l0.x + x0.y * l0.y + x0.z * l0.z + x0.w * l0.w
                    + x1.x * l1.x + x1.y * l1.y + x1.z * l1.z + x1.w * l1.w;
#pragma unroll
            for (int o = 16; o > 0; o >>= 1)
                d += __shfl_xor_sync(0xffffffffu, d, o);
            if (lane == 0) g_sL[r] = d + g_cLR;
        }
    }
}

// ---------------- CSR chain (stream B) ----------------
__global__ void k_hist(const void* __restrict__ ei, int E) {
    int e = blockIdx.x * blockDim.x + threadIdx.x;
    if (e >= E) return;
    int r = ld_row(ei, e, g_is64);
    atomicAdd(&g_cnt[r], 1);
}

__global__ void k_scan(int B) {
    __shared__ int s[1024];
    int t = threadIdx.x;
    int CH = (B + 1023) >> 10;
    int lo = t * CH, hi = min(lo + CH, B);
    int sum = 0;
    for (int i = lo; i < hi; i++) sum += g_cnt[i];
    s[t] = sum;
    __syncthreads();
    for (int off = 1; off < 1024; off <<= 1) {
        int v = (t >= off) ? s[t - off] : 0;
        __syncthreads();
        s[t] += v;
        __syncthreads();
    }
    int run = (t == 0) ? 0 : s[t - 1];
    for (int i = lo; i < hi; i++) { g_off[i] = run; run += g_cnt[i]; }
    if (t == 1023) g_off[B] = s[1023];
}

__global__ void k_scatter(const void* __restrict__ ei, int E) {
    int e = blockIdx.x * blockDim.x + threadIdx.x;
    if (e >= E) return;
    int r = ld_row(ei, e, g_is64);
    int pos = atomicAdd(&g_cur[r], 1);
    g_csr[g_off[r] + pos] = e;
}

// ---------------- warp-register bitonic sort of 64 ints (2/lane) -----------
__device__ __forceinline__ void bitonic64(int& v0, int& v1, int lane) {
#pragma unroll
    for (int k = 2; k <= 32; k <<= 1) {
#pragma unroll
        for (int j = k >> 1; j > 0; j >>= 1) {
            bool low = ((lane & j) == 0);
            int x0 = __shfl_xor_sync(0xffffffffu, v0, j);
            bool asc0 = ((lane & k) == 0);
            v0 = (asc0 == low) ? min(v0, x0) : max(v0, x0);
            int x1 = __shfl_xor_sync(0xffffffffu, v1, j);
            bool asc1 = (k == 32) ? false : asc0;
            v1 = (asc1 == low) ? min(v1, x1) : max(v1, x1);
        }
    }
    { int mn = min(v0, v1), mx = max(v0, v1); v0 = mn; v1 = mx; }
#pragma unroll
    for (int j = 16; j > 0; j >>= 1) {
        bool low = ((lane & j) == 0);
        int x0 = __shfl_xor_sync(0xffffffffu, v0, j);
        v0 = low ? min(v0, x0) : max(v0, x0);
        int x1 = __shfl_xor_sync(0xffffffffu, v1, j);
        v1 = low ? min(v1, x1) : max(v1, x1);
    }
}

// ---------------- k_agg (R9 structure, 1 warp/row) ----------------
__global__ void __launch_bounds__(256) k_agg(const void* __restrict__ ei,
                                             int E, int B) {
    __shared__ int   s_e[8][128];
    __shared__ float s_a[8][128];
    int t = threadIdx.x, w = t >> 5, lane = t & 31;
    int r = blockIdx.x * 8 + w;
    if (r >= B) return;
    int is64 = g_is64;
    int off0 = g_off[r];
    int deg = g_off[r + 1] - off0;
    float base = g_sL[r];

    const uint4* eh = (const uint4*)g_enth;
    float4 A0 = make_float4(0.f, 0.f, 0.f, 0.f);
    float4 A1 = make_float4(0.f, 0.f, 0.f, 0.f);
    float asum = 0.f;

#define ACC(q, a) do { \
        float2 f0 = __half22float2(*(__half2*)&(q).x); \
        float2 f1 = __half22float2(*(__half2*)&(q).y); \
        float2 f2 = __half22float2(*(__half2*)&(q).z); \
        float2 f3 = __half22float2(*(__half2*)&(q).w); \
        A0.x = fmaf((a), f0.x, A0.x); A0.y = fmaf((a), f0.y, A0.y); \
        A0.z = fmaf((a), f1.x, A0.z); A0.w = fmaf((a), f1.y, A0.w); \
        A1.x = fmaf((a), f2.x, A1.x); A1.y = fmaf((a), f2.y, A1.y); \
        A1.z = fmaf((a), f3.x, A1.z); A1.w = fmaf((a), f3.y, A1.w); \
    } while (0)

#define GATHER_LOOP() do { \
        int i = 0; \
        for (; i + 4 <= deg; i += 4) { \
            int c0 = s_e[w][i],     c1 = s_e[w][i + 1]; \
            int c2 = s_e[w][i + 2], c3 = s_e[w][i + 3]; \
            uint4 q0 = __ldg(&eh[(size_t)c0 * 32 + lane]); \
            uint4 q1 = __ldg(&eh[(size_t)c1 * 32 + lane]); \
            uint4 q2 = __ldg(&eh[(size_t)c2 * 32 + lane]); \
            uint4 q3 = __ldg(&eh[(size_t)c3 * 32 + lane]); \
            float a0 = s_a[w][i],     a1 = s_a[w][i + 1]; \
            float a2 = s_a[w][i + 2], a3 = s_a[w][i + 3]; \
            ACC(q0, a0); ACC(q1, a1); ACC(q2, a2); ACC(q3, a3); \
        } \
        for (; i < deg; i++) { \
            int c = s_e[w][i]; \
            float a = s_a[w][i]; \
            uint4 q = __ldg(&eh[(size_t)c * 32 + lane]); \
            ACC(q, a); \
        } \
    } while (0)

    if (deg <= 64) {
        int v0 = (lane < deg) ? g_csr[off0 + lane] : 0x7fffffff;
        int v1 = (32 + lane < deg) ? g_csr[off0 + 32 + lane] : 0x7fffffff;
        bitonic64(v0, v1, lane);
        float ap = 0.f;
        if (lane < deg) {
            int c = ld_col(ei, E, v0, is64);
            float s = base + g_dR[c];
            float v = s >= 0.f ? s : 0.2f * s;
            float a = __expf(-v);
            s_e[w][lane] = c; s_a[w][lane] = a;
            ap += a;
        }
        if (32 + lane < deg) {
            int c = ld_col(ei, E, v1, is64);
            float s = base + g_dR[c];
            float v = s >= 0.f ? s : 0.2f * s;
            float a = __expf(-v);
            s_e[w][32 + lane] = c; s_a[w][32 + lane] = a;
            ap += a;
        }
#pragma unroll
        for (int o = 16; o > 0; o >>= 1)
            ap += __shfl_xor_sync(0xffffffffu, ap, o);
        asum = ap;
        __syncwarp();
        GATHER_LOOP();
    } else if (deg <= 128) {
        int P = 1;
        while (P < deg) P <<= 1;
        for (int i = lane; i < P; i += 32)
            s_e[w][i] = (i < deg) ? g_csr[off0 + i] : 0x7fffffff;
        __syncwarp();
        for (int k = 2; k <= P; k <<= 1) {
            for (int j = k >> 1; j > 0; j >>= 1) {
                for (int i = lane; i < P; i += 32) {
                    int ixj = i ^ j;
                    if (ixj > i) {
                        int a = s_e[w][i], c = s_e[w][ixj];
                        bool up = ((i & k) == 0);
                        if ((a > c) == up) { s_e[w][i] = c; s_e[w][ixj] = a; }
                    }
                }
                __syncwarp();
            }
        }
        float ap = 0.f;
        for (int i = lane; i < deg; i += 32) {
            int e = s_e[w][i];
            int c = ld_col(ei, E, e, is64);
            float s = base + g_dR[c];
            float v = s >= 0.f ? s : 0.2f * s;
            float a = __expf(-v);
            s_e[w][i] = c;
            s_a[w][i] = a;
            ap += a;
        }
#pragma unroll
        for (int o = 16; o > 0; o >>= 1)
            ap += __shfl_xor_sync(0xffffffffu, ap, o);
        asum = ap;
        __syncwarp();
        GATHER_LOOP();
    } else {
        // deterministic fallback: increasing edge-id selection (rare)
        int last = -1;
        for (int rk = 0; rk < deg; rk++) {
            int m = 0x7fffffff;
            for (int i = lane; i < deg; i += 32) {
                int ec = g_csr[off0 + i];
                if (ec > last && ec < m) m = ec;
            }
#pragma unroll
            for (int o = 16; o > 0; o >>= 1)
                m = min(m, __shfl_xor_sync(0xffffffffu, m, o));
            int c = ld_col(ei, E, m, is64);
            float s = base + g_dR[c];
            float v = s >= 0.f ? s : 0.2f * s;
            float a = __expf(-v);
            uint4 q = __ldg(&eh[(size_t)c * 32 + lane]);
            asum += a;
            ACC(q, a);
            last = m;
        }
    }
#undef GATHER_LOOP
#undef ACC

    float inv = 1.0f / asum;
    __half2 h0 = __floats2half2_rn(A0.x * inv, A0.y * inv);
    __half2 h1 = __floats2half2_rn(A0.z * inv, A0.w * inv);
    __half2 h2 = __floats2half2_rn(A1.x * inv, A1.y * inv);
    __half2 h3 = __floats2half2_rn(A1.z * inv, A1.w * inv);
    uint4 q;
    q.x = *(unsigned*)&h0; q.y = *(unsigned*)&h1;
    q.z = *(unsigned*)&h2; q.w = *(unsigned*)&h3;
    ((uint4*)g_Yh)[(size_t)r * 32 + lane] = q;
}

// ---------------- k_gemm: HMMA m16n8k16 ----------------
__global__ void __launch_bounds__(256) k_gemm(const float* __restrict__ bias,
                                              const float* __restrict__ prelu,
                                              float* __restrict__ out, int M) {
    int tid = threadIdx.x;
    int wid = tid >> 5, lane = tid & 31;
    int gid = lane >> 2, tig = lane & 3;
    int mbase = blockIdx.x * 128 + wid * 16;
    int r0 = mbase + gid, r1 = r0 + 8;
    bool p0 = r0 < M, p1 = r1 < M;

    float acc[16][4];
#pragma unroll
    for (int nf = 0; nf < 16; nf++)
#pragma unroll
        for (int j = 0; j < 4; j++) acc[nf][j] = 0.f;

    const __half* Yh = g_Yh;
    const uint2* Wf = (const uint2*)g_Wfrag;

    for (int ks = 0; ks < 16; ks++) {
        int k0 = ks * 16 + tig * 2;
        unsigned a0 = p0 ? *(const unsigned*)&Yh[(size_t)r0 * IN_DIM + k0] : 0u;
        unsigned a1 = p1 ? *(const unsigned*)&Yh[(size_t)r1 * IN_DIM + k0] : 0u;
        unsigned a2 = p0 ? *(const unsigned*)&Yh[(size_t)r0 * IN_DIM + k0 + 8] : 0u;
        unsigned a3 = p1 ? *(const unsigned*)&Yh[(size_t)r1 * IN_DIM + k0 + 8] : 0u;
#pragma unroll
        for (int nf = 0; nf < 16; nf++) {
            uint2 bb = __ldg(&Wf[(ks * 16 + nf) * 32 + lane]);
            asm volatile(
                "mma.sync.aligned.m16n8k16.row.col.f32.f16.f16.f32 "
                "{%0,%1,%2,%3}, {%4,%5,%6,%7}, {%8,%9}, {%0,%1,%2,%3};"
                : "+f"(acc[nf][0]), "+f"(acc[nf][1]),
                  "+f"(acc[nf][2]), "+f"(acc[nf][3])
                : "r"(a0), "r"(a1), "r"(a2), "r"(a3),
                  "r"(bb.x), "r"(bb.y));
        }
    }

    float pw = prelu[0];
#pragma unroll
    for (int nf = 0; nf < 16; nf++) {
        int n0 = nf * 8 + tig * 2;
        float bv0 = __ldg(&bias[n0]), bv1 = __ldg(&bias[n0 + 1]);
        if (p0) {
            float v0 = acc[nf][0] + bv0, v1 = acc[nf][1] + bv1;
            float2 o;
            o.x = v0 >= 0.f ? v0 : pw * v0;
            o.y = v1 >= 0.f ? v1 : pw * v1;
            *(float2*)&out[(size_t)r0 * OUT_DIM + n0] = o;
        }
        if (p1) {
            float v2 = acc[nf][2] + bv0, v3 = acc[nf][3] + bv1;
            float2 o;
            o.x = v2 >= 0.f ? v2 : pw * v2;
            o.y = v3 >= 0.f ? v3 : pw * v3;
            *(float2*)&out[(size_t)r1 * OUT_DIM + n0] = o;
        }
    }
}

// ---------------- launch (R9 structure: CSR chain forked on stream B) ------
extern "C" void kernel_launch(void* const* d_in, const int* in_sizes, int n_in,
                              void* d_out, int out_size) {
    const float* ent  = (const float*)d_in[0];
    const void*  bids = d_in[1];
    const void*  ei   = d_in[2];
    const float* W    = (const float*)d_in[3];
    const float* bias = (const float*)d_in[4];
    const float* wa   = (const float*)d_in[5];
    const float* pw   = (const float*)d_in[6];

    int KG = in_sizes[0] / IN_DIM;
    int B  = in_sizes[1];
    int E  = in_sizes[2] / 2;
    if (KG > KG_MAX) KG = KG_MAX;
    if (B > B_MAX) B = B_MAX;
    if (E > E_MAX) E = E_MAX;

    int nbdr = (KG + 31) / 32;
    int nbsl = (B + 7) / 8;

    cudaStream_t s2;
    cudaEvent_t ev1, ev2;
    cudaStreamCreateWithFlags(&s2, cudaStreamNonBlocking);
    cudaEventCreateWithFlags(&ev1, cudaEventDisableTiming);
    cudaEventCreateWithFlags(&ev2, cudaEventDisableTiming);

    k_prep<<<1, 256>>>(bids, W, bias, wa, B);
    cudaEventRecord(ev1, 0);
    cudaStreamWaitEvent(s2, ev1, 0);

    // stream B: CSR chain (atomic/latency-bound)
    k_hist<<<(E + 255) / 256, 256, 0, s2>>>(ei, E);
    k_scan<<<1, 1024, 0, s2>>>(B);
    k_scatter<<<(E + 255) / 256, 256, 0, s2>>>(ei, E);
    cudaEventRecord(ev2, s2);

    // stream A (default): BW-bound embedding pass, concurrent with CSR chain
    k_fused<<<nbdr + nbsl, 256>>>(ent, bids, KG, B, nbdr);

    cudaStreamWaitEvent(0, ev2, 0);
    k_agg<<<(B + 7) / 8, 256>>>(ei, E, B);
    k_gemm<<<(B + 127) / 128, 256>>>(bias, pw, (float*)d_out, B);

    cudaEventDestroy(ev1);
    cudaEventDestroy(ev2);
    cudaStreamDestroy(s2);
}

// round 13
// speedup vs baseline: 1.2385x; 1.1384x over previous
#include <cuda_runtime.h>
#include <cuda_fp16.h>
#include <stdint.h>

#define KG_MAX 200000
#define B_MAX  20000
#define E_MAX  640000
#define IN_DIM 256
#define OUT_DIM 128

// ---------------- device scratch ----------------
__device__ int   g_is64;
__device__ __align__(16) float g_vL[IN_DIM];
__device__ __align__(16) float g_vR[IN_DIM];
__device__ float g_cLR;
__device__ float g_dR[KG_MAX];
__device__ float g_sL[B_MAX];
__device__ int   g_cnt[B_MAX];
__device__ int   g_cur[B_MAX];
__device__ int   g_off[B_MAX + 1];
__device__ int   g_csr[E_MAX];
__device__ __align__(16) __half g_enth[(size_t)KG_MAX * IN_DIM];
__device__ __align__(16) __half g_Yh[(size_t)B_MAX * IN_DIM];
__device__ __align__(16) unsigned g_Wfrag[16 * 16 * 32 * 2];

__device__ __forceinline__ int ld_row(const void* p, int e, int is64) {
    return is64 ? (int)((const long long*)p)[e] : ((const int*)p)[e];
}
__device__ __forceinline__ int ld_col(const void* p, int E, int e, int is64) {
    return is64 ? (int)((const long long*)p)[(long long)E + e]
                : ((const int*)p)[E + e];
}

// ---------------- k_prep ----------------
__global__ void k_prep(const void* __restrict__ bids,
                       const float* __restrict__ W,
                       const float* __restrict__ bias,
                       const float* __restrict__ wa,
                       int B) {
    int t = threadIdx.x;  // 256
    __shared__ int s_nz;
    if (t == 0) s_nz = 0;
    __syncthreads();
    const unsigned int* u = (const unsigned int*)bids;
    if (u[2 * t + 1] != 0u) atomicOr(&s_nz, 1);
    __syncthreads();
    if (t == 0) g_is64 = s_nz ? 0 : 1;

    float vl = 0.f, vr = 0.f;
#pragma unroll 4
    for (int n = 0; n < OUT_DIM; n++) {
        float w = W[n * IN_DIM + t];
        vl = fmaf(w, wa[n], vl);
        vr = fmaf(w, wa[OUT_DIM + n], vr);
    }
    g_vL[t] = vl;
    g_vR[t] = vr;

    __shared__ float sr[256];
    sr[t] = (t < OUT_DIM) ? bias[t] * (wa[t] + wa[t + OUT_DIM]) : 0.f;
    __syncthreads();
    for (int off = 128; off > 0; off >>= 1) {
        if (t < off) sr[t] += sr[t + off];
        __syncthreads();
    }
    if (t == 0) g_cLR = sr[0];

    // pack W into mma.m16n8k16 B-fragment order (fp16)
    for (int f = t; f < 16 * 16 * 32 * 2; f += 256) {
        int q = f & 1;
        int lane = (f >> 1) & 31;
        int nf = (f >> 6) & 15;
        int ks = f >> 10;
        int n = nf * 8 + (lane >> 2);
        int k = ks * 16 + (lane & 3) * 2 + (q ? 8 : 0);
        __half2 h = __floats2half2_rn(W[n * IN_DIM + k], W[n * IN_DIM + k + 1]);
        g_Wfrag[f] = *(unsigned*)&h;
    }
    for (int i = t; i < B; i += 256) { g_cnt[i] = 0; g_cur[i] = 0; }
}

// ---------------- k_fused v1: dR + fp16 convert + sL (stream A) -----------
__global__ void __launch_bounds__(256) k_fused(
        const float* __restrict__ ent, const void* __restrict__ bids,
        int KG, int B, int nbdr) {
    int bid = blockIdx.x;
    int t = threadIdx.x, w = t >> 5, lane = t & 31;
    if (bid < nbdr) {
        int v = bid * 8 + w;
        if (v < KG) {
            const float* x = ent + (size_t)v * IN_DIM + lane * 8;
            float4 x0 = *(const float4*)x;
            float4 x1 = *(const float4*)(x + 4);
            float4 r0 = *(const float4*)&g_vR[lane * 8];
            float4 r1 = *(const float4*)&g_vR[lane * 8 + 4];
            float d = x0.x * r0.x + x0.y * r0.y + x0.z * r0.z + x0.w * r0.w
                    + x1.x * r1.x + x1.y * r1.y + x1.z * r1.z + x1.w * r1.w;
#pragma unroll
            for (int o = 16; o > 0; o >>= 1)
                d += __shfl_xor_sync(0xffffffffu, d, o);
            if (lane == 0) g_dR[v] = d;
            __half2 h0 = __floats2half2_rn(x0.x, x0.y);
            __half2 h1 = __floats2half2_rn(x0.z, x0.w);
            __half2 h2 = __floats2half2_rn(x1.x, x1.y);
            __half2 h3 = __floats2half2_rn(x1.z, x1.w);
            uint4 q;
            q.x = *(unsigned int*)&h0; q.y = *(unsigned int*)&h1;
            q.z = *(unsigned int*)&h2; q.w = *(unsigned int*)&h3;
            ((uint4*)g_enth)[(size_t)v * 32 + lane] = q;
        }
    } else {
        int r = (bid - nbdr) * 8 + w;
        if (r < B) {
            long long gi = g_is64 ? ((const long long*)bids)[r]
                                  : (long long)((const int*)bids)[r];
            const float* x = ent + gi * (long long)IN_DIM + lane * 8;
            float4 x0 = *(const float4*)x;
            float4 x1 = *(const float4*)(x + 4);
            float4 l0 = *(const float4*)&g_vL[lane * 8];
            float4 l1 = *(const float4*)&g_vL[lane * 8 + 4];
            float d = x0.x * l0.x + x0.y * l0.y + x0.z * l0.z + x0.w * l0.w
                    + x1.x * l1.x + x1.y * l1.y + x1.z * l1.z + x1.w * l1.w;
#pragma unroll
            for (int o = 16; o > 0; o >>= 1)
                d += __shfl_xor_sync(0xffffffffu, d, o);
            if (lane == 0) g_sL[r] = d + g_cLR;
        }
    }
}

// ---------------- CSR chain (stream B) ----------------
__global__ void k_hist(const void* __restrict__ ei, int E) {
    int e = blockIdx.x * blockDim.x + threadIdx.x;
    if (e >= E) return;
    int r = ld_row(ei, e, g_is64);
    atomicAdd(&g_cnt[r], 1);
}

__global__ void k_scan(int B) {
    __shared__ int s[1024];
    int t = threadIdx.x;
    int CH = (B + 1023) >> 10;
    int lo = t * CH, hi = min(lo + CH, B);
    int sum = 0;
    for (int i = lo; i < hi; i++) sum += g_cnt[i];
    s[t] = sum;
    __syncthreads();
    for (int off = 1; off < 1024; off <<= 1) {
        int v = (t >= off) ? s[t - off] : 0;
        __syncthreads();
        s[t] += v;
        __syncthreads();
    }
    int run = (t == 0) ? 0 : s[t - 1];
    for (int i = lo; i < hi; i++) { g_off[i] = run; run += g_cnt[i]; }
    if (t == 1023) g_off[B] = s[1023];
}

__global__ void k_scatter(const void* __restrict__ ei, int E) {
    int e = blockIdx.x * blockDim.x + threadIdx.x;
    if (e >= E) return;
    int r = ld_row(ei, e, g_is64);
    int pos = atomicAdd(&g_cur[r], 1);
    g_csr[g_off[r] + pos] = e;
}

// ---------------- warp-register bitonic sort of 64 ints (2/lane) -----------
__device__ __forceinline__ void bitonic64(int& v0, int& v1, int lane) {
#pragma unroll
    for (int k = 2; k <= 32; k <<= 1) {
#pragma unroll
        for (int j = k >> 1; j > 0; j >>= 1) {
            bool low = ((lane & j) == 0);
            int x0 = __shfl_xor_sync(0xffffffffu, v0, j);
            bool asc0 = ((lane & k) == 0);
            v0 = (asc0 == low) ? min(v0, x0) : max(v0, x0);
            int x1 = __shfl_xor_sync(0xffffffffu, v1, j);
            bool asc1 = (k == 32) ? false : asc0;
            v1 = (asc1 == low) ? min(v1, x1) : max(v1, x1);
        }
    }
    { int mn = min(v0, v1), mx = max(v0, v1); v0 = mn; v1 = mx; }
#pragma unroll
    for (int j = 16; j > 0; j >>= 1) {
        bool low = ((lane & j) == 0);
        int x0 = __shfl_xor_sync(0xffffffffu, v0, j);
        v0 = low ? min(v0, x0) : max(v0, x0);
        int x1 = __shfl_xor_sync(0xffffffffu, v1, j);
        v1 = low ? min(v1, x1) : max(v1, x1);
    }
}

// ---------------- k_agg2: 2 warps per row (measured 58.6us in R10) ---------
// 4 rows/block. Warp pair (h=0,1) redundantly sorts + computes att (private
// smem), then partitions the gather by 4-edge-group parity. Partials merged
// in fixed order after a single uniform __syncthreads -> deterministic.
__global__ void __launch_bounds__(256) k_agg2(const void* __restrict__ ei,
                                              int E, int B) {
    __shared__ int   s_e[8][128];
    __shared__ float s_a[8][128];
    __shared__ float s_m[4][256];
    int t = threadIdx.x, wp = t >> 5, lane = t & 31;
    int rl = wp >> 1, h = wp & 1;
    int r = blockIdx.x * 4 + rl;
    bool valid = (r < B);

    const uint4* eh = (const uint4*)g_enth;
    float4 A0 = make_float4(0.f, 0.f, 0.f, 0.f);
    float4 A1 = make_float4(0.f, 0.f, 0.f, 0.f);
    float asum = 1.f;

#define ACC(q, a) do { \
        float2 f0 = __half22float2(*(__half2*)&(q).x); \
        float2 f1 = __half22float2(*(__half2*)&(q).y); \
        float2 f2 = __half22float2(*(__half2*)&(q).z); \
        float2 f3 = __half22float2(*(__half2*)&(q).w); \
        A0.x = fmaf((a), f0.x, A0.x); A0.y = fmaf((a), f0.y, A0.y); \
        A0.z = fmaf((a), f1.x, A0.z); A0.w = fmaf((a), f1.y, A0.w); \
        A1.x = fmaf((a), f2.x, A1.x); A1.y = fmaf((a), f2.y, A1.y); \
        A1.z = fmaf((a), f3.x, A1.z); A1.w = fmaf((a), f3.y, A1.w); \
    } while (0)

    // groups of 4 edges; warp h handles groups with (g & 1) == h
#define GATHER_PAR() do { \
        for (int gs = h * 4; gs + 4 <= deg; gs += 8) { \
            int c0 = s_e[wp][gs],     c1 = s_e[wp][gs + 1]; \
            int c2 = s_e[wp][gs + 2], c3 = s_e[wp][gs + 3]; \
            uint4 q0 = __ldg(&eh[(size_t)c0 * 32 + lane]); \
            uint4 q1 = __ldg(&eh[(size_t)c1 * 32 + lane]); \
            uint4 q2 = __ldg(&eh[(size_t)c2 * 32 + lane]); \
            uint4 q3 = __ldg(&eh[(size_t)c3 * 32 + lane]); \
            float a0 = s_a[wp][gs],     a1 = s_a[wp][gs + 1]; \
            float a2 = s_a[wp][gs + 2], a3 = s_a[wp][gs + 3]; \
            ACC(q0, a0); ACC(q1, a1); ACC(q2, a2); ACC(q3, a3); \
        } \
        int tg = deg & ~3; \
        if (tg < deg && (((tg >> 2) & 1) == h)) { \
            for (int i = tg; i < deg; i++) { \
                int c = s_e[wp][i]; \
                uint4 q = __ldg(&eh[(size_t)c * 32 + lane]); \
                ACC(q, s_a[wp][i]); \
            } \
        } \
    } while (0)

    if (valid) {
        int is64 = g_is64;
        int off0 = g_off[r];
        int deg = g_off[r + 1] - off0;
        float base = g_sL[r];

        if (deg <= 64) {
            int v0 = (lane < deg) ? g_csr[off0 + lane] : 0x7fffffff;
            int v1 = (32 + lane < deg) ? g_csr[off0 + 32 + lane] : 0x7fffffff;
            bitonic64(v0, v1, lane);
            float ap = 0.f;
            if (lane < deg) {
                int c = ld_col(ei, E, v0, is64);
                float s = base + g_dR[c];
                float v = s >= 0.f ? s : 0.2f * s;
                float a = __expf(-v);
                s_e[wp][lane] = c; s_a[wp][lane] = a;
                ap += a;
            }
            if (32 + lane < deg) {
                int c = ld_col(ei, E, v1, is64);
                float s = base + g_dR[c];
                float v = s >= 0.f ? s : 0.2f * s;
                float a = __expf(-v);
                s_e[wp][32 + lane] = c; s_a[wp][32 + lane] = a;
                ap += a;
            }
#pragma unroll
            for (int o = 16; o > 0; o >>= 1)
                ap += __shfl_xor_sync(0xffffffffu, ap, o);
            asum = ap;
            __syncwarp();
            GATHER_PAR();
        } else if (deg <= 128) {
            int P = 1;
            while (P < deg) P <<= 1;
            for (int i = lane; i < P; i += 32)
                s_e[wp][i] = (i < deg) ? g_csr[off0 + i] : 0x7fffffff;
            __syncwarp();
            for (int k = 2; k <= P; k <<= 1) {
                for (int j = k >> 1; j > 0; j >>= 1) {
                    for (int i = lane; i < P; i += 32) {
                        int ixj = i ^ j;
                        if (ixj > i) {
                            int a = s_e[wp][i], c = s_e[wp][ixj];
                            bool up = ((i & k) == 0);
                            if ((a > c) == up) { s_e[wp][i] = c; s_e[wp][ixj] = a; }
                        }
                    }
                    __syncwarp();
                }
            }
            float ap = 0.f;
            for (int i = lane; i < deg; i += 32) {
                int e = s_e[wp][i];
                int c = ld_col(ei, E, e, is64);
                float s = base + g_dR[c];
                float v = s >= 0.f ? s : 0.2f * s;
                float a = __expf(-v);
                s_e[wp][i] = c;
                s_a[wp][i] = a;
                ap += a;
            }
#pragma unroll
            for (int o = 16; o > 0; o >>= 1)
                ap += __shfl_xor_sync(0xffffffffu, ap, o);
            asum = ap;
            __syncwarp();
            GATHER_PAR();
        } else {
            // deterministic fallback: serial increasing edge-id (both warps
            // run selection redundantly; parity-partitioned accumulation)
            int last = -1;
            float as = 0.f;
            for (int rk = 0; rk < deg; rk++) {
                int m = 0x7fffffff;
                for (int i = lane; i < deg; i += 32) {
                    int ec = g_csr[off0 + i];
                    if (ec > last && ec < m) m = ec;
                }
#pragma unroll
                for (int o = 16; o > 0; o >>= 1)
                    m = min(m, __shfl_xor_sync(0xffffffffu, m, o));
                int c = ld_col(ei, E, m, is64);
                float s = base + g_dR[c];
                float v = s >= 0.f ? s : 0.2f * s;
                float a = __expf(-v);
                as += a;
                if (((rk >> 2) & 1) == h) {
                    uint4 q = __ldg(&eh[(size_t)c * 32 + lane]);
                    ACC(q, a);
                }
                last = m;
            }
            asum = as;
        }
    }
#undef GATHER_PAR
#undef ACC

    // partner (h=1) publishes its partial
    if (valid && h == 1) {
        float* mp = &s_m[rl][lane * 8];
        *(float4*)mp = A0;
        *(float4*)(mp + 4) = A1;
    }
    __syncthreads();   // uniform: every warp reaches exactly once
    if (valid && h == 0) {
        const float* mp = &s_m[rl][lane * 8];
        float4 B0 = *(const float4*)mp;
        float4 B1 = *(const float4*)(mp + 4);
        A0.x += B0.x; A0.y += B0.y; A0.z += B0.z; A0.w += B0.w;
        A1.x += B1.x; A1.y += B1.y; A1.z += B1.z; A1.w += B1.w;
        float inv = 1.0f / asum;
        __half2 h0 = __floats2half2_rn(A0.x * inv, A0.y * inv);
        __half2 h1 = __floats2half2_rn(A0.z * inv, A0.w * inv);
        __half2 h2 = __floats2half2_rn(A1.x * inv, A1.y * inv);
        __half2 h3 = __floats2half2_rn(A1.z * inv, A1.w * inv);
        uint4 q;
        q.x = *(unsigned*)&h0; q.y = *(unsigned*)&h1;
        q.z = *(unsigned*)&h2; q.w = *(unsigned*)&h3;
        ((uint4*)g_Yh)[(size_t)r * 32 + lane] = q;
    }
}

// ---------------- k_gemm: HMMA m16n8k16 ----------------
__global__ void __launch_bounds__(256) k_gemm(const float* __restrict__ bias,
                                              const float* __restrict__ prelu,
                                              float* __restrict__ out, int M) {
    int tid = threadIdx.x;
    int wid = tid >> 5, lane = tid & 31;
    int gid = lane >> 2, tig = lane & 3;
    int mbase = blockIdx.x * 128 + wid * 16;
    int r0 = mbase + gid, r1 = r0 + 8;
    bool p0 = r0 < M, p1 = r1 < M;

    float acc[16][4];
#pragma unroll
    for (int nf = 0; nf < 16; nf++)
#pragma unroll
        for (int j = 0; j < 4; j++) acc[nf][j] = 0.f;

    const __half* Yh = g_Yh;
    const uint2* Wf = (const uint2*)g_Wfrag;

    for (int ks = 0; ks < 16; ks++) {
        int k0 = ks * 16 + tig * 2;
        unsigned a0 = p0 ? *(const unsigned*)&Yh[(size_t)r0 * IN_DIM + k0] : 0u;
        unsigned a1 = p1 ? *(const unsigned*)&Yh[(size_t)r1 * IN_DIM + k0] : 0u;
        unsigned a2 = p0 ? *(const unsigned*)&Yh[(size_t)r0 * IN_DIM + k0 + 8] : 0u;
        unsigned a3 = p1 ? *(const unsigned*)&Yh[(size_t)r1 * IN_DIM + k0 + 8] : 0u;
#pragma unroll
        for (int nf = 0; nf < 16; nf++) {
            uint2 bb = __ldg(&Wf[(ks * 16 + nf) * 32 + lane]);
            asm volatile(
                "mma.sync.aligned.m16n8k16.row.col.f32.f16.f16.f32 "
                "{%0,%1,%2,%3}, {%4,%5,%6,%7}, {%8,%9}, {%0,%1,%2,%3};"
                : "+f"(acc[nf][0]), "+f"(acc[nf][1]),
                  "+f"(acc[nf][2]), "+f"(acc[nf][3])
                : "r"(a0), "r"(a1), "r"(a2), "r"(a3),
                  "r"(bb.x), "r"(bb.y));
        }
    }

    float pw = prelu[0];
#pragma unroll
    for (int nf = 0; nf < 16; nf++) {
        int n0 = nf * 8 + tig * 2;
        float bv0 = __ldg(&bias[n0]), bv1 = __ldg(&bias[n0 + 1]);
        if (p0) {
            float v0 = acc[nf][0] + bv0, v1 = acc[nf][1] + bv1;
            float2 o;
            o.x = v0 >= 0.f ? v0 : pw * v0;
            o.y = v1 >= 0.f ? v1 : pw * v1;
            *(float2*)&out[(size_t)r0 * OUT_DIM + n0] = o;
        }
        if (p1) {
            float v2 = acc[nf][2] + bv0, v3 = acc[nf][3] + bv1;
            float2 o;
            o.x = v2 >= 0.f ? v2 : pw * v2;
            o.y = v3 >= 0.f ? v3 : pw * v3;
            *(float2*)&out[(size_t)r1 * OUT_DIM + n0] = o;
        }
    }
}

// ---------------- launch (R9 structure: CSR chain forked on stream B) ------
extern "C" void kernel_launch(void* const* d_in, const int* in_sizes, int n_in,
                              void* d_out, int out_size) {
    const float* ent  = (const float*)d_in[0];
    const void*  bids = d_in[1];
    const void*  ei   = d_in[2];
    const float* W    = (const float*)d_in[3];
    const float* bias = (const float*)d_in[4];
    const float* wa   = (const float*)d_in[5];
    const float* pw   = (const float*)d_in[6];

    int KG = in_sizes[0] / IN_DIM;
    int B  = in_sizes[1];
    int E  = in_sizes[2] / 2;
    if (KG > KG_MAX) KG = KG_MAX;
    if (B > B_MAX) B = B_MAX;
    if (E > E_MAX) E = E_MAX;

    int nbdr = (KG + 7) / 8;
    int nbsl = (B + 7) / 8;

    cudaStream_t s2;
    cudaEvent_t ev1, ev2;
    cudaStreamCreateWithFlags(&s2, cudaStreamNonBlocking);
    cudaEventCreateWithFlags(&ev1, cudaEventDisableTiming);
    cudaEventCreateWithFlags(&ev2, cudaEventDisableTiming);

    k_prep<<<1, 256>>>(bids, W, bias, wa, B);
    cudaEventRecord(ev1, 0);
    cudaStreamWaitEvent(s2, ev1, 0);

    // stream B: CSR chain (atomic/latency-bound)
    k_hist<<<(E + 255) / 256, 256, 0, s2>>>(ei, E);
    k_scan<<<1, 1024, 0, s2>>>(B);
    k_scatter<<<(E + 255) / 256, 256, 0, s2>>>(ei, E);
    cudaEventRecord(ev2, s2);

    // stream A (default): BW-bound embedding pass, concurrent with CSR chain
    k_fused<<<nbdr + nbsl, 256>>>(ent, bids, KG, B, nbdr);

    cudaStreamWaitEvent(0, ev2, 0);
    k_agg2<<<(B + 3) / 4, 256>>>(ei, E, B);
    k_gemm<<<(B + 127) / 128, 256>>>(bias, pw, (float*)d_out, B);

    cudaEventDestroy(ev1);
    cudaEventDestroy(ev2);
    cudaStreamDestroy(s2);
}

// round 14
// speedup vs baseline: 1.2530x; 1.0117x over previous
#include <cuda_runtime.h>
#include <cuda_fp16.h>
#include <stdint.h>

#define KG_MAX 200000
#define B_MAX  20000
#define E_MAX  640000
#define IN_DIM 256
#define OUT_DIM 128

// ---------------- device scratch ----------------
__device__ int   g_is64;
__device__ __align__(16) float g_vL[IN_DIM];
__device__ __align__(16) float g_vR[IN_DIM];
__device__ float g_cLR;
__device__ float g_dR[KG_MAX];
__device__ float g_sL[B_MAX];
__device__ int   g_cnt[B_MAX];
__device__ int   g_cur[B_MAX];
__device__ int   g_off[B_MAX + 1];
__device__ int   g_csr[E_MAX];
__device__ __align__(16) __half g_enth[(size_t)KG_MAX * IN_DIM];
__device__ __align__(16) __half g_Yh[(size_t)B_MAX * IN_DIM];
__device__ __align__(16) unsigned g_Wfrag[16 * 16 * 32 * 2];

__device__ __forceinline__ int ld_row(const void* p, int e, int is64) {
    return is64 ? (int)((const long long*)p)[e] : ((const int*)p)[e];
}
__device__ __forceinline__ int ld_col(const void* p, int E, int e, int is64) {
    return is64 ? (int)((const long long*)p)[(long long)E + e]
                : ((const int*)p)[E + e];
}

// ---------------- k_prep ----------------
__global__ void k_prep(const void* __restrict__ bids,
                       const float* __restrict__ W,
                       const float* __restrict__ bias,
                       const float* __restrict__ wa,
                       int B) {
    int t = threadIdx.x;  // 256
    __shared__ int s_nz;
    if (t == 0) s_nz = 0;
    __syncthreads();
    const unsigned int* u = (const unsigned int*)bids;
    if (u[2 * t + 1] != 0u) atomicOr(&s_nz, 1);
    __syncthreads();
    if (t == 0) g_is64 = s_nz ? 0 : 1;

    float vl = 0.f, vr = 0.f;
#pragma unroll 4
    for (int n = 0; n < OUT_DIM; n++) {
        float w = W[n * IN_DIM + t];
        vl = fmaf(w, wa[n], vl);
        vr = fmaf(w, wa[OUT_DIM + n], vr);
    }
    g_vL[t] = vl;
    g_vR[t] = vr;

    __shared__ float sr[256];
    sr[t] = (t < OUT_DIM) ? bias[t] * (wa[t] + wa[t + OUT_DIM]) : 0.f;
    __syncthreads();
    for (int off = 128; off > 0; off >>= 1) {
        if (t < off) sr[t] += sr[t + off];
        __syncthreads();
    }
    if (t == 0) g_cLR = sr[0];

    // pack W into mma.m16n8k16 B-fragment order (fp16)
    for (int f = t; f < 16 * 16 * 32 * 2; f += 256) {
        int q = f & 1;
        int lane = (f >> 1) & 31;
        int nf = (f >> 6) & 15;
        int ks = f >> 10;
        int n = nf * 8 + (lane >> 2);
        int k = ks * 16 + (lane & 3) * 2 + (q ? 8 : 0);
        __half2 h = __floats2half2_rn(W[n * IN_DIM + k], W[n * IN_DIM + k + 1]);
        g_Wfrag[f] = *(unsigned*)&h;
    }
    for (int i = t; i < B; i += 256) { g_cnt[i] = 0; g_cur[i] = 0; }
}

// ---------------- k_fused v1: dR + fp16 convert + sL (stream A) -----------
__global__ void __launch_bounds__(256) k_fused(
        const float* __restrict__ ent, const void* __restrict__ bids,
        int KG, int B, int nbdr) {
    int bid = blockIdx.x;
    int t = threadIdx.x, w = t >> 5, lane = t & 31;
    if (bid < nbdr) {
        int v = bid * 8 + w;
        if (v < KG) {
            const float* x = ent + (size_t)v * IN_DIM + lane * 8;
            float4 x0 = *(const float4*)x;
            float4 x1 = *(const float4*)(x + 4);
            float4 r0 = *(const float4*)&g_vR[lane * 8];
            float4 r1 = *(const float4*)&g_vR[lane * 8 + 4];
            float d = x0.x * r0.x + x0.y * r0.y + x0.z * r0.z + x0.w * r0.w
                    + x1.x * r1.x + x1.y * r1.y + x1.z * r1.z + x1.w * r1.w;
#pragma unroll
            for (int o = 16; o > 0; o >>= 1)
                d += __shfl_xor_sync(0xffffffffu, d, o);
            if (lane == 0) g_dR[v] = d;
            __half2 h0 = __floats2half2_rn(x0.x, x0.y);
            __half2 h1 = __floats2half2_rn(x0.z, x0.w);
            __half2 h2 = __floats2half2_rn(x1.x, x1.y);
            __half2 h3 = __floats2half2_rn(x1.z, x1.w);
            uint4 q;
            q.x = *(unsigned int*)&h0; q.y = *(unsigned int*)&h1;
            q.z = *(unsigned int*)&h2; q.w = *(unsigned int*)&h3;
            ((uint4*)g_enth)[(size_t)v * 32 + lane] = q;
        }
    } else {
        int r = (bid - nbdr) * 8 + w;
        if (r < B) {
            long long gi = g_is64 ? ((const long long*)bids)[r]
                                  : (long long)((const int*)bids)[r];
            const float* x = ent + gi * (long long)IN_DIM + lane * 8;
            float4 x0 = *(const float4*)x;
            float4 x1 = *(const float4*)(x + 4);
            float4 l0 = *(const float4*)&g_vL[lane * 8];
            float4 l1 = *(const float4*)&g_vL[lane * 8 + 4];
            float d = x0.x * l0.x + x0.y * l0.y + x0.z * l0.z + x0.w * l0.w
                    + x1.x * l1.x + x1.y * l1.y + x1.z * l1.z + x1.w * l1.w;
#pragma unroll
            for (int o = 16; o > 0; o >>= 1)
                d += __shfl_xor_sync(0xffffffffu, d, o);
            if (lane == 0) g_sL[r] = d + g_cLR;
        }
    }
}

// ---------------- CSR chain (stream B) ----------------
__global__ void k_hist(const void* __restrict__ ei, int E) {
    int e = blockIdx.x * blockDim.x + threadIdx.x;
    if (e >= E) return;
    int r = ld_row(ei, e, g_is64);
    atomicAdd(&g_cnt[r], 1);
}

__global__ void k_scan(int B) {
    __shared__ int s[1024];
    int t = threadIdx.x;
    int CH = (B + 1023) >> 10;
    int lo = t * CH, hi = min(lo + CH, B);
    int sum = 0;
    for (int i = lo; i < hi; i++) sum += g_cnt[i];
    s[t] = sum;
    __syncthreads();
    for (int off = 1; off < 1024; off <<= 1) {
        int v = (t >= off) ? s[t - off] : 0;
        __syncthreads();
        s[t] += v;
        __syncthreads();
    }
    int run = (t == 0) ? 0 : s[t - 1];
    for (int i = lo; i < hi; i++) { g_off[i] = run; run += g_cnt[i]; }
    if (t == 1023) g_off[B] = s[1023];
}

__global__ void k_scatter(const void* __restrict__ ei, int E) {
    int e = blockIdx.x * blockDim.x + threadIdx.x;
    if (e >= E) return;
    int r = ld_row(ei, e, g_is64);
    int pos = atomicAdd(&g_cur[r], 1);
    g_csr[g_off[r] + pos] = e;
}

// ---------------- warp-register bitonic sort of 64 ints (2/lane) -----------
__device__ __forceinline__ void bitonic64(int& v0, int& v1, int lane) {
#pragma unroll
    for (int k = 2; k <= 32; k <<= 1) {
#pragma unroll
        for (int j = k >> 1; j > 0; j >>= 1) {
            bool low = ((lane & j) == 0);
            int x0 = __shfl_xor_sync(0xffffffffu, v0, j);
            bool asc0 = ((lane & k) == 0);
            v0 = (asc0 == low) ? min(v0, x0) : max(v0, x0);
            int x1 = __shfl_xor_sync(0xffffffffu, v1, j);
            bool asc1 = (k == 32) ? false : asc0;
            v1 = (asc1 == low) ? min(v1, x1) : max(v1, x1);
        }
    }
    { int mn = min(v0, v1), mx = max(v0, v1); v0 = mn; v1 = mx; }
#pragma unroll
    for (int j = 16; j > 0; j >>= 1) {
        bool low = ((lane & j) == 0);
        int x0 = __shfl_xor_sync(0xffffffffu, v0, j);
        v0 = low ? min(v0, x0) : max(v0, x0);
        int x1 = __shfl_xor_sync(0xffffffffu, v1, j);
        v1 = low ? min(v1, x1) : max(v1, x1);
    }
}

// ---------------- k_agg2: 2 warps per row (measured 58.6us in R10) ---------
// 4 rows/block. Warp pair (h=0,1) redundantly sorts + computes att (private
// smem), then partitions the gather by 4-edge-group parity. Partials merged
// in fixed order after a single uniform __syncthreads -> deterministic.
__global__ void __launch_bounds__(256) k_agg2(const void* __restrict__ ei,
                                              int E, int B) {
    __shared__ int   s_e[8][128];
    __shared__ float s_a[8][128];
    __shared__ float s_m[4][256];
    int t = threadIdx.x, wp = t >> 5, lane = t & 31;
    int rl = wp >> 1, h = wp & 1;
    int r = blockIdx.x * 4 + rl;
    bool valid = (r < B);

    const uint4* eh = (const uint4*)g_enth;
    float4 A0 = make_float4(0.f, 0.f, 0.f, 0.f);
    float4 A1 = make_float4(0.f, 0.f, 0.f, 0.f);
    float asum = 1.f;

#define ACC(q, a) do { \
        float2 f0 = __half22float2(*(__half2*)&(q).x); \
        float2 f1 = __half22float2(*(__half2*)&(q).y); \
        float2 f2 = __half22float2(*(__half2*)&(q).z); \
        float2 f3 = __half22float2(*(__half2*)&(q).w); \
        A0.x = fmaf((a), f0.x, A0.x); A0.y = fmaf((a), f0.y, A0.y); \
        A0.z = fmaf((a), f1.x, A0.z); A0.w = fmaf((a), f1.y, A0.w); \
        A1.x = fmaf((a), f2.x, A1.x); A1.y = fmaf((a), f2.y, A1.y); \
        A1.z = fmaf((a), f3.x, A1.z); A1.w = fmaf((a), f3.y, A1.w); \
    } while (0)

    // groups of 4 edges; warp h handles groups with (g & 1) == h
#define GATHER_PAR() do { \
        for (int gs = h * 4; gs + 4 <= deg; gs += 8) { \
            int c0 = s_e[wp][gs],     c1 = s_e[wp][gs + 1]; \
            int c2 = s_e[wp][gs + 2], c3 = s_e[wp][gs + 3]; \
            uint4 q0 = __ldg(&eh[(size_t)c0 * 32 + lane]); \
            uint4 q1 = __ldg(&eh[(size_t)c1 * 32 + lane]); \
            uint4 q2 = __ldg(&eh[(size_t)c2 * 32 + lane]); \
            uint4 q3 = __ldg(&eh[(size_t)c3 * 32 + lane]); \
            float a0 = s_a[wp][gs],     a1 = s_a[wp][gs + 1]; \
            float a2 = s_a[wp][gs + 2], a3 = s_a[wp][gs + 3]; \
            ACC(q0, a0); ACC(q1, a1); ACC(q2, a2); ACC(q3, a3); \
        } \
        int tg = deg & ~3; \
        if (tg < deg && (((tg >> 2) & 1) == h)) { \
            for (int i = tg; i < deg; i++) { \
                int c = s_e[wp][i]; \
                uint4 q = __ldg(&eh[(size_t)c * 32 + lane]); \
                ACC(q, s_a[wp][i]); \
            } \
        } \
    } while (0)

    if (valid) {
        int is64 = g_is64;
        int off0 = g_off[r];
        int deg = g_off[r + 1] - off0;
        float base = g_sL[r];

        if (deg <= 64) {
            int v0 = (lane < deg) ? g_csr[off0 + lane] : 0x7fffffff;
            int v1 = (32 + lane < deg) ? g_csr[off0 + 32 + lane] : 0x7fffffff;
            bitonic64(v0, v1, lane);
            float ap = 0.f;
            if (lane < deg) {
                int c = ld_col(ei, E, v0, is64);
                float s = base + g_dR[c];
                float v = s >= 0.f ? s : 0.2f * s;
                float a = __expf(-v);
                s_e[wp][lane] = c; s_a[wp][lane] = a;
                ap += a;
            }
            if (32 + lane < deg) {
                int c = ld_col(ei, E, v1, is64);
                float s = base + g_dR[c];
                float v = s >= 0.f ? s : 0.2f * s;
                float a = __expf(-v);
                s_e[wp][32 + lane] = c; s_a[wp][32 + lane] = a;
                ap += a;
            }
#pragma unroll
            for (int o = 16; o > 0; o >>= 1)
                ap += __shfl_xor_sync(0xffffffffu, ap, o);
            asum = ap;
            __syncwarp();
            GATHER_PAR();
        } else if (deg <= 128) {
            int P = 1;
            while (P < deg) P <<= 1;
            for (int i = lane; i < P; i += 32)
                s_e[wp][i] = (i < deg) ? g_csr[off0 + i] : 0x7fffffff;
            __syncwarp();
            for (int k = 2; k <= P; k <<= 1) {
                for (int j = k >> 1; j > 0; j >>= 1) {
                    for (int i = lane; i < P; i += 32) {
                        int ixj = i ^ j;
                        if (ixj > i) {
                            int a = s_e[wp][i], c = s_e[wp][ixj];
                            bool up = ((i & k) == 0);
                            if ((a > c) == up) { s_e[wp][i] = c; s_e[wp][ixj] = a; }
                        }
                    }
                    __syncwarp();
                }
            }
            float ap = 0.f;
            for (int i = lane; i < deg; i += 32) {
                int e = s_e[wp][i];
                int c = ld_col(ei, E, e, is64);
                float s = base + g_dR[c];
                float v = s >= 0.f ? s : 0.2f * s;
                float a = __expf(-v);
                s_e[wp][i] = c;
                s_a[wp][i] = a;
                ap += a;
            }
#pragma unroll
            for (int o = 16; o > 0; o >>= 1)
                ap += __shfl_xor_sync(0xffffffffu, ap, o);
            asum = ap;
            __syncwarp();
            GATHER_PAR();
        } else {
            // deterministic fallback: serial increasing edge-id (both warps
            // run selection redundantly; parity-partitioned accumulation)
            int last = -1;
            float as = 0.f;
            for (int rk = 0; rk < deg; rk++) {
                int m = 0x7fffffff;
                for (int i = lane; i < deg; i += 32) {
                    int ec = g_csr[off0 + i];
                    if (ec > last && ec < m) m = ec;
                }
#pragma unroll
                for (int o = 16; o > 0; o >>= 1)
                    m = min(m, __shfl_xor_sync(0xffffffffu, m, o));
                int c = ld_col(ei, E, m, is64);
                float s = base + g_dR[c];
                float v = s >= 0.f ? s : 0.2f * s;
                float a = __expf(-v);
                as += a;
                if (((rk >> 2) & 1) == h) {
                    uint4 q = __ldg(&eh[(size_t)c * 32 + lane]);
                    ACC(q, a);
                }
                last = m;
            }
            asum = as;
        }
    }
#undef GATHER_PAR
#undef ACC

    // partner (h=1) publishes its partial
    if (valid && h == 1) {
        float* mp = &s_m[rl][lane * 8];
        *(float4*)mp = A0;
        *(float4*)(mp + 4) = A1;
    }
    __syncthreads();   // uniform: every warp reaches exactly once
    if (valid && h == 0) {
        const float* mp = &s_m[rl][lane * 8];
        float4 B0 = *(const float4*)mp;
        float4 B1 = *(const float4*)(mp + 4);
        A0.x += B0.x; A0.y += B0.y; A0.z += B0.z; A0.w += B0.w;
        A1.x += B1.x; A1.y += B1.y; A1.z += B1.z; A1.w += B1.w;
        float inv = 1.0f / asum;
        __half2 h0 = __floats2half2_rn(A0.x * inv, A0.y * inv);
        __half2 h1 = __floats2half2_rn(A0.z * inv, A0.w * inv);
        __half2 h2 = __floats2half2_rn(A1.x * inv, A1.y * inv);
        __half2 h3 = __floats2half2_rn(A1.z * inv, A1.w * inv);
        uint4 q;
        q.x = *(unsigned*)&h0; q.y = *(unsigned*)&h1;
        q.z = *(unsigned*)&h2; q.w = *(unsigned*)&h3;
        ((uint4*)g_Yh)[(size_t)r * 32 + lane] = q;
    }
}

// ---------------- k_gemm: HMMA m16n8k16 ----------------
__global__ void __launch_bounds__(256) k_gemm(const float* __restrict__ bias,
                                              const float* __restrict__ prelu,
                                              float* __restrict__ out, int M) {
    int tid = threadIdx.x;
    int wid = tid >> 5, lane = tid & 31;
    int gid = lane >> 2, tig = lane & 3;
    int mbase = blockIdx.x * 128 + wid * 16;
    int r0 = mbase + gid, r1 = r0 + 8;
    bool p0 = r0 < M, p1 = r1 < M;

    float acc[16][4];
#pragma unroll
    for (int nf = 0; nf < 16; nf++)
#pragma unroll
        for (int j = 0; j < 4; j++) acc[nf][j] = 0.f;

    const __half* Yh = g_Yh;
    const uint2* Wf = (const uint2*)g_Wfrag;

    for (int ks = 0; ks < 16; ks++) {
        int k0 = ks * 16 + tig * 2;
        unsigned a0 = p0 ? *(const unsigned*)&Yh[(size_t)r0 * IN_DIM + k0] : 0u;
        unsigned a1 = p1 ? *(const unsigned*)&Yh[(size_t)r1 * IN_DIM + k0] : 0u;
        unsigned a2 = p0 ? *(const unsigned*)&Yh[(size_t)r0 * IN_DIM + k0 + 8] : 0u;
        unsigned a3 = p1 ? *(const unsigned*)&Yh[(size_t)r1 * IN_DIM + k0 + 8] : 0u;
#pragma unroll
        for (int nf = 0; nf < 16; nf++) {
            uint2 bb = __ldg(&Wf[(ks * 16 + nf) * 32 + lane]);
            asm volatile(
                "mma.sync.aligned.m16n8k16.row.col.f32.f16.f16.f32 "
                "{%0,%1,%2,%3}, {%4,%5,%6,%7}, {%8,%9}, {%0,%1,%2,%3};"
                : "+f"(acc[nf][0]), "+f"(acc[nf][1]),
                  "+f"(acc[nf][2]), "+f"(acc[nf][3])
                : "r"(a0), "r"(a1), "r"(a2), "r"(a3),
                  "r"(bb.x), "r"(bb.y));
        }
    }

    float pw = prelu[0];
#pragma unroll
    for (int nf = 0; nf < 16; nf++) {
        int n0 = nf * 8 + tig * 2;
        float bv0 = __ldg(&bias[n0]), bv1 = __ldg(&bias[n0 + 1]);
        if (p0) {
            float v0 = acc[nf][0] + bv0, v1 = acc[nf][1] + bv1;
            float2 o;
            o.x = v0 >= 0.f ? v0 : pw * v0;
            o.y = v1 >= 0.f ? v1 : pw * v1;
            *(float2*)&out[(size_t)r0 * OUT_DIM + n0] = o;
        }
        if (p1) {
            float v2 = acc[nf][2] + bv0, v3 = acc[nf][3] + bv1;
            float2 o;
            o.x = v2 >= 0.f ? v2 : pw * v2;
            o.y = v3 >= 0.f ? v3 : pw * v3;
            *(float2*)&out[(size_t)r1 * OUT_DIM + n0] = o;
        }
    }
}

// ---------------- launch (R9 structure: CSR chain forked on stream B) ------
extern "C" void kernel_launch(void* const* d_in, const int* in_sizes, int n_in,
                              void* d_out, int out_size) {
    const float* ent  = (const float*)d_in[0];
    const void*  bids = d_in[1];
    const void*  ei   = d_in[2];
    const float* W    = (const float*)d_in[3];
    const float* bias = (const float*)d_in[4];
    const float* wa   = (const float*)d_in[5];
    const float* pw   = (const float*)d_in[6];

    int KG = in_sizes[0] / IN_DIM;
    int B  = in_sizes[1];
    int E  = in_sizes[2] / 2;
    if (KG > KG_MAX) KG = KG_MAX;
    if (B > B_MAX) B = B_MAX;
    if (E > E_MAX) E = E_MAX;

    int nbdr = (KG + 7) / 8;
    int nbsl = (B + 7) / 8;

    cudaStream_t s2;
    cudaEvent_t ev1, ev2;
    cudaStreamCreateWithFlags(&s2, cudaStreamNonBlocking);
    cudaEventCreateWithFlags(&ev1, cudaEventDisableTiming);
    cudaEventCreateWithFlags(&ev2, cudaEventDisableTiming);

    k_prep<<<1, 256>>>(bids, W, bias, wa, B);
    cudaEventRecord(ev1, 0);
    cudaStreamWaitEvent(s2, ev1, 0);

    // stream B: CSR chain (atomic/latency-bound)
    k_hist<<<(E + 255) / 256, 256, 0, s2>>>(ei, E);
    k_scan<<<1, 1024, 0, s2>>>(B);
    k_scatter<<<(E + 255) / 256, 256, 0, s2>>>(ei, E);
    cudaEventRecord(ev2, s2);

    // stream A (default): BW-bound embedding pass, concurrent with CSR chain
    k_fused<<<nbdr + nbsl, 256>>>(ent, bids, KG, B, nbdr);

    cudaStreamWaitEvent(0, ev2, 0);
    k_agg2<<<(B + 3) / 4, 256>>>(ei, E, B);
    k_gemm<<<(B + 127) / 128, 256>>>(bias, pw, (float*)d_out, B);

    cudaEventDestroy(ev1);
    cudaEventDestroy(ev2);
    cudaStreamDestroy(s2);
}